// round 1
// baseline (speedup 1.0000x reference)
#include <cuda_runtime.h>
#include <math.h>

// Problem constants
#define Bq 8
#define Nq 2048
#define Cq 384
#define Hq 6
#define Dq 64
#define Mq (Bq * Nq)      // 16384 tokens
#define QKVq (3 * Cq)     // 1152
#define BHq (Bq * Hq)     // 48

// Scratch (device globals: no allocation allowed)
__device__ float g_q[BHq * Nq * Dq];
__device__ float g_k[BHq * Nq * Dq];
__device__ float g_v[BHq * Nq * Dq];
__device__ float g_ctx[(size_t)Mq * Cq];

// ---------------------------------------------------------------------------
// Kernel 1: fused QKV projection.  qkv[t][j] = sum_c x[t][c] * w_qkv[j][c]
// 64x64 output tile per CTA, 256 threads, 4x4 micro-tile, K-chunk = 16.
// Results scattered directly into per-head [B,H,N,D] layout.
// ---------------------------------------------------------------------------
__global__ __launch_bounds__(256) void qkv_gemm_kernel(
    const float* __restrict__ x, const float* __restrict__ w)
{
    __shared__ float As[16][64];
    __shared__ float Bs[16][64];

    const int tid = threadIdx.x;
    const int m0 = blockIdx.y * 64;   // token tile
    const int j0 = blockIdx.x * 64;   // qkv-col tile
    const int lm = tid >> 2;          // 0..63
    const int lk = (tid & 3) * 4;     // 0,4,8,12
    const int ty = tid >> 4;          // 0..15
    const int tx = tid & 15;          // 0..15

    float acc[4][4];
#pragma unroll
    for (int i = 0; i < 4; i++)
#pragma unroll
        for (int j = 0; j < 4; j++) acc[i][j] = 0.f;

    for (int k0 = 0; k0 < Cq; k0 += 16) {
        float4 av = *(const float4*)&x[(size_t)(m0 + lm) * Cq + k0 + lk];
        float4 bv = *(const float4*)&w[(size_t)(j0 + lm) * Cq + k0 + lk];
        __syncthreads();
        As[lk + 0][lm] = av.x; As[lk + 1][lm] = av.y;
        As[lk + 2][lm] = av.z; As[lk + 3][lm] = av.w;
        Bs[lk + 0][lm] = bv.x; Bs[lk + 1][lm] = bv.y;
        Bs[lk + 2][lm] = bv.z; Bs[lk + 3][lm] = bv.w;
        __syncthreads();
#pragma unroll
        for (int kk = 0; kk < 16; kk++) {
            float4 a = *(float4*)&As[kk][ty * 4];
            float4 b = *(float4*)&Bs[kk][tx * 4];
            float aa[4] = {a.x, a.y, a.z, a.w};
            float bb[4] = {b.x, b.y, b.z, b.w};
#pragma unroll
            for (int i = 0; i < 4; i++)
#pragma unroll
                for (int j = 0; j < 4; j++) acc[i][j] += aa[i] * bb[j];
        }
    }

    // Scatter into q/k/v [B,H,N,D].  Tile is entirely within one (s,h) pair.
    const int jbase = j0 + tx * 4;
    const int s = jbase / Cq;             // 0,1,2 -> q,k,v
    const int h = (jbase % Cq) / Dq;
    const int d0 = jbase % Dq;            // multiple of 4
    float* dst = (s == 0) ? g_q : ((s == 1) ? g_k : g_v);

#pragma unroll
    for (int i = 0; i < 4; i++) {
        int t = m0 + ty * 4 + i;
        int b = t >> 11;                  // /Nq
        int n = t & (Nq - 1);
        float4 v4 = make_float4(acc[i][0], acc[i][1], acc[i][2], acc[i][3]);
        *(float4*)&dst[(((size_t)b * Hq + h) * Nq + n) * Dq + d0] = v4;
    }
}

// ---------------------------------------------------------------------------
// Kernel 2: fused attention.  One CTA = one (b,h) x 16 query rows.
// Full 16x2048 fp32 score strip lives in dynamic smem; single softmax pass;
// normalized attn written straight to d_out; AV accumulated in registers.
// ---------------------------------------------------------------------------
#define SMEM_FLOATS (16 * 2048 + 16 * 64 + 64 * 132)   // 42240 floats = 168960 B

__global__ __launch_bounds__(256) void attn_kernel(float* __restrict__ attnp)
{
    extern __shared__ float sm[];
    float* Ssm = sm;                         // [16][2048]
    float* Qs  = sm + 16 * 2048;             // [16][64]
    float* Ks  = Qs + 16 * 64;               // [64][132] transposed K tile / V tile + partials

    const int tid = threadIdx.x;
    const int bh = blockIdx.y;               // 0..47
    const int q0 = blockIdx.x * 16;
    const int b = bh / Hq;
    const int h = bh - b * Hq;

    const float* qptr = g_q + (size_t)bh * Nq * Dq;
    const float* kptr = g_k + (size_t)bh * Nq * Dq;
    const float* vptr = g_v + (size_t)bh * Nq * Dq;

    // Load Q tile [16][64]
    {
        int r = tid >> 4, d4 = (tid & 15) * 4;
        *(float4*)&Qs[r * 64 + d4] = *(const float4*)&qptr[(size_t)(q0 + r) * Dq + d4];
    }
    __syncthreads();

    const float scale = 0.125f;   // D^-0.5

    // ---- Phase 1: scores S[16][2048] ----
    for (int kt = 0; kt < Nq; kt += 128) {
        // Load K tile transposed: Ks[d][c] (stride 132), c=0..127 keys
#pragma unroll
        for (int i = 0; i < 8; i++) {
            int idx = tid + i * 256;
            int c = idx >> 4;
            int d4 = (idx & 15) * 4;
            float4 kv = *(const float4*)&kptr[(size_t)(kt + c) * Dq + d4];
            Ks[(d4 + 0) * 132 + c] = kv.x;
            Ks[(d4 + 1) * 132 + c] = kv.y;
            Ks[(d4 + 2) * 132 + c] = kv.z;
            Ks[(d4 + 3) * 132 + c] = kv.w;
        }
        __syncthreads();

        const int r0 = (tid >> 5) * 2;     // 0,2,..,14
        const int c0 = (tid & 31) * 4;     // 0..124
        float a0[4] = {0.f, 0.f, 0.f, 0.f};
        float a1[4] = {0.f, 0.f, 0.f, 0.f};
#pragma unroll 8
        for (int d = 0; d < 64; d++) {
            float4 k4 = *(float4*)&Ks[d * 132 + c0];
            float qa = Qs[r0 * 64 + d];
            float qb = Qs[(r0 + 1) * 64 + d];
            a0[0] += qa * k4.x; a0[1] += qa * k4.y; a0[2] += qa * k4.z; a0[3] += qa * k4.w;
            a1[0] += qb * k4.x; a1[1] += qb * k4.y; a1[2] += qb * k4.z; a1[3] += qb * k4.w;
        }
        *(float4*)&Ssm[r0 * 2048 + kt + c0] =
            make_float4(a0[0] * scale, a0[1] * scale, a0[2] * scale, a0[3] * scale);
        *(float4*)&Ssm[(r0 + 1) * 2048 + kt + c0] =
            make_float4(a1[0] * scale, a1[1] * scale, a1[2] * scale, a1[3] * scale);
        __syncthreads();
    }

    // ---- Softmax (16 threads per row, strided float4) ----
    {
        const int r = tid >> 4;
        const int g = tid & 15;
        float mx = -1e30f;
#pragma unroll 4
        for (int i = 0; i < 32; i++) {
            float4 v = *(float4*)&Ssm[r * 2048 + g * 4 + i * 64];
            mx = fmaxf(mx, fmaxf(fmaxf(v.x, v.y), fmaxf(v.z, v.w)));
        }
#pragma unroll
        for (int off = 8; off >= 1; off >>= 1)
            mx = fmaxf(mx, __shfl_xor_sync(0xffffffffu, mx, off, 16));

        float sum = 0.f;
#pragma unroll 4
        for (int i = 0; i < 32; i++) {
            int c = g * 4 + i * 64;
            float4 v = *(float4*)&Ssm[r * 2048 + c];
            v.x = __expf(v.x - mx); v.y = __expf(v.y - mx);
            v.z = __expf(v.z - mx); v.w = __expf(v.w - mx);
            sum += v.x + v.y + v.z + v.w;
            *(float4*)&Ssm[r * 2048 + c] = v;
        }
#pragma unroll
        for (int off = 8; off >= 1; off >>= 1)
            sum += __shfl_xor_sync(0xffffffffu, sum, off, 16);
        float inv = 1.f / sum;

        float* aprow = attnp ? attnp + ((size_t)bh * Nq + (q0 + r)) * (size_t)Nq : (float*)0;
#pragma unroll 4
        for (int i = 0; i < 32; i++) {
            int c = g * 4 + i * 64;
            float4 v = *(float4*)&Ssm[r * 2048 + c];
            v.x *= inv; v.y *= inv; v.z *= inv; v.w *= inv;
            *(float4*)&Ssm[r * 2048 + c] = v;
            if (aprow) *(float4*)&aprow[c] = v;
        }
    }
    __syncthreads();

    // ---- Phase 2: AV.  4 key-groups x 64 threads, 4r x 4c per thread. ----
    float* Vs = Ks;               // [64][64]
    float* Ps = Ks + 64 * 64;     // partials for groups 1..3: 3*16*64 floats

    const int grp = tid >> 6;     // 0..3  (kk quarter)
    const int lt = tid & 63;
    const int rr = (lt >> 4) * 4; // 0,4,8,12
    const int cc = (lt & 15) * 4; // 0..60

    float acc[4][4];
#pragma unroll
    for (int i = 0; i < 4; i++)
#pragma unroll
        for (int j = 0; j < 4; j++) acc[i][j] = 0.f;

    for (int vt = 0; vt < Nq; vt += 64) {
        __syncthreads();
#pragma unroll
        for (int i = 0; i < 4; i++) {
            int idx = tid + i * 256;
            int kk = idx >> 4;
            int c4 = (idx & 15) * 4;
            *(float4*)&Vs[kk * 64 + c4] = *(const float4*)&vptr[(size_t)(vt + kk) * Dq + c4];
        }
        __syncthreads();
#pragma unroll
        for (int kk = 0; kk < 16; kk++) {
            int kg = grp * 16 + kk;
            float4 v4 = *(float4*)&Vs[kg * 64 + cc];
            float s0 = Ssm[(rr + 0) * 2048 + vt + kg];
            float s1 = Ssm[(rr + 1) * 2048 + vt + kg];
            float s2 = Ssm[(rr + 2) * 2048 + vt + kg];
            float s3 = Ssm[(rr + 3) * 2048 + vt + kg];
            acc[0][0] += s0 * v4.x; acc[0][1] += s0 * v4.y; acc[0][2] += s0 * v4.z; acc[0][3] += s0 * v4.w;
            acc[1][0] += s1 * v4.x; acc[1][1] += s1 * v4.y; acc[1][2] += s1 * v4.z; acc[1][3] += s1 * v4.w;
            acc[2][0] += s2 * v4.x; acc[2][1] += s2 * v4.y; acc[2][2] += s2 * v4.z; acc[2][3] += s2 * v4.w;
            acc[3][0] += s3 * v4.x; acc[3][1] += s3 * v4.y; acc[3][2] += s3 * v4.z; acc[3][3] += s3 * v4.w;
        }
    }

    __syncthreads();
    if (grp > 0) {
#pragma unroll
        for (int i = 0; i < 4; i++) {
            *(float4*)&Ps[((grp - 1) * 16 + rr + i) * 64 + cc] =
                make_float4(acc[i][0], acc[i][1], acc[i][2], acc[i][3]);
        }
    }
    __syncthreads();
    if (grp == 0) {
#pragma unroll
        for (int i = 0; i < 4; i++) {
            float4 t0 = *(float4*)&Ps[(0 * 16 + rr + i) * 64 + cc];
            float4 t1 = *(float4*)&Ps[(1 * 16 + rr + i) * 64 + cc];
            float4 t2 = *(float4*)&Ps[(2 * 16 + rr + i) * 64 + cc];
            float4 o;
            o.x = acc[i][0] + t0.x + t1.x + t2.x;
            o.y = acc[i][1] + t0.y + t1.y + t2.y;
            o.z = acc[i][2] + t0.z + t1.z + t2.z;
            o.w = acc[i][3] + t0.w + t1.w + t2.w;
            size_t tok = (size_t)b * Nq + (q0 + rr + i);
            *(float4*)&g_ctx[tok * Cq + h * Dq + cc] = o;
        }
    }
}

// ---------------------------------------------------------------------------
// Kernel 3: output projection. out[t][j] = sum_c ctx[t][c] * w_proj[j][c] + b[j]
// ---------------------------------------------------------------------------
__global__ __launch_bounds__(256) void proj_gemm_kernel(
    const float* __restrict__ w, const float* __restrict__ bias,
    float* __restrict__ out)
{
    __shared__ float As[16][64];
    __shared__ float Bs[16][64];

    const int tid = threadIdx.x;
    const int m0 = blockIdx.y * 64;
    const int j0 = blockIdx.x * 64;
    const int lm = tid >> 2;
    const int lk = (tid & 3) * 4;
    const int ty = tid >> 4;
    const int tx = tid & 15;

    float acc[4][4];
#pragma unroll
    for (int i = 0; i < 4; i++)
#pragma unroll
        for (int j = 0; j < 4; j++) acc[i][j] = 0.f;

    for (int k0 = 0; k0 < Cq; k0 += 16) {
        float4 av = *(const float4*)&g_ctx[(size_t)(m0 + lm) * Cq + k0 + lk];
        float4 bv = *(const float4*)&w[(size_t)(j0 + lm) * Cq + k0 + lk];
        __syncthreads();
        As[lk + 0][lm] = av.x; As[lk + 1][lm] = av.y;
        As[lk + 2][lm] = av.z; As[lk + 3][lm] = av.w;
        Bs[lk + 0][lm] = bv.x; Bs[lk + 1][lm] = bv.y;
        Bs[lk + 2][lm] = bv.z; Bs[lk + 3][lm] = bv.w;
        __syncthreads();
#pragma unroll
        for (int kk = 0; kk < 16; kk++) {
            float4 a = *(float4*)&As[kk][ty * 4];
            float4 b4 = *(float4*)&Bs[kk][tx * 4];
            float aa[4] = {a.x, a.y, a.z, a.w};
            float bb[4] = {b4.x, b4.y, b4.z, b4.w};
#pragma unroll
            for (int i = 0; i < 4; i++)
#pragma unroll
                for (int j = 0; j < 4; j++) acc[i][j] += aa[i] * bb[j];
        }
    }

    float4 bv = *(const float4*)&bias[j0 + tx * 4];
#pragma unroll
    for (int i = 0; i < 4; i++) {
        float4 o = make_float4(acc[i][0] + bv.x, acc[i][1] + bv.y,
                               acc[i][2] + bv.z, acc[i][3] + bv.w);
        *(float4*)&out[(size_t)(m0 + ty * 4 + i) * Cq + j0 + tx * 4] = o;
    }
}

// ---------------------------------------------------------------------------
extern "C" void kernel_launch(void* const* d_in, const int* in_sizes, int n_in,
                              void* d_out, int out_size)
{
    const float* x      = (const float*)d_in[0];   // [8,2048,384]
    const float* w_qkv  = (const float*)d_in[1];   // [1152,384]
    const float* w_proj = (const float*)d_in[2];   // [384,384]
    const float* b_proj = (const float*)d_in[3];   // [384]

    const size_t out_elems  = (size_t)Mq * Cq;                 // 6,291,456
    const size_t attn_elems = (size_t)BHq * Nq * (size_t)Nq;   // 201,326,592

    float* outp  = nullptr;
    float* attnp = nullptr;
    if ((size_t)out_size >= out_elems + attn_elems) {
        outp  = (float*)d_out;
        attnp = (float*)d_out + out_elems;
    } else if ((size_t)out_size == attn_elems) {
        attnp = (float*)d_out;
    } else {
        outp = (float*)d_out;
    }

    // K1: QKV projection
    qkv_gemm_kernel<<<dim3(QKVq / 64, Mq / 64), 256>>>(x, w_qkv);

    // K2: fused attention (dynamic smem)
    static const int smem_bytes = SMEM_FLOATS * 4;
    cudaFuncSetAttribute(attn_kernel, cudaFuncAttributeMaxDynamicSharedMemorySize,
                         smem_bytes);
    attn_kernel<<<dim3(Nq / 16, BHq), 256, smem_bytes>>>(attnp);

    // K3: output projection
    if (outp) {
        proj_gemm_kernel<<<dim3(Cq / 64, Mq / 64), 256>>>(w_proj, b_proj, outp);
    }
}

// round 2
// speedup vs baseline: 1.5356x; 1.5356x over previous
#include <cuda_runtime.h>
#include <math.h>
#include <stdint.h>

// Problem constants
#define Bq 8
#define Nq 2048
#define Cq 384
#define Hq 6
#define Dq 64
#define Mq (Bq * Nq)      // 16384 tokens
#define QKVq (3 * Cq)     // 1152
#define BHq (Bq * Hq)     // 48

// smem strides (words), chosen for bank-conflict-free fragment access
#define SSTR 2052   // scores strip stride: 2052%32=4 -> a-frag rows hit distinct banks
#define QSTR 65
#define KSTR 68     // 68%32=4 -> b-frag keys hit distinct banks

// Scratch (device globals: no allocation allowed)
__device__ float g_q[BHq * Nq * Dq];
__device__ float g_k[BHq * Nq * Dq];
__device__ float g_v[BHq * Nq * Dq];
__device__ float g_ctx[(size_t)Mq * Cq];

// ---------------------------------------------------------------------------
// tf32 helpers
// ---------------------------------------------------------------------------
__device__ __forceinline__ uint32_t f2tf(float x) {
    uint32_t r;
    asm("cvt.rna.tf32.f32 %0, %1;" : "=r"(r) : "f"(x));
    return r;
}

__device__ __forceinline__ void mma8(float* d, const uint32_t* a, const uint32_t* b) {
    asm volatile(
        "mma.sync.aligned.m16n8k8.row.col.f32.tf32.tf32.f32 "
        "{%0,%1,%2,%3},{%4,%5,%6,%7},{%8,%9},{%0,%1,%2,%3};"
        : "+f"(d[0]), "+f"(d[1]), "+f"(d[2]), "+f"(d[3])
        : "r"(a[0]), "r"(a[1]), "r"(a[2]), "r"(a[3]), "r"(b[0]), "r"(b[1]));
}

// ---------------------------------------------------------------------------
// Kernel 1: fused QKV projection (fp32 SIMT, unchanged from R1)
// ---------------------------------------------------------------------------
__global__ __launch_bounds__(256) void qkv_gemm_kernel(
    const float* __restrict__ x, const float* __restrict__ w)
{
    __shared__ float As[16][64];
    __shared__ float Bs[16][64];

    const int tid = threadIdx.x;
    const int m0 = blockIdx.y * 64;
    const int j0 = blockIdx.x * 64;
    const int lm = tid >> 2;
    const int lk = (tid & 3) * 4;
    const int ty = tid >> 4;
    const int tx = tid & 15;

    float acc[4][4];
#pragma unroll
    for (int i = 0; i < 4; i++)
#pragma unroll
        for (int j = 0; j < 4; j++) acc[i][j] = 0.f;

    for (int k0 = 0; k0 < Cq; k0 += 16) {
        float4 av = *(const float4*)&x[(size_t)(m0 + lm) * Cq + k0 + lk];
        float4 bv = *(const float4*)&w[(size_t)(j0 + lm) * Cq + k0 + lk];
        __syncthreads();
        As[lk + 0][lm] = av.x; As[lk + 1][lm] = av.y;
        As[lk + 2][lm] = av.z; As[lk + 3][lm] = av.w;
        Bs[lk + 0][lm] = bv.x; Bs[lk + 1][lm] = bv.y;
        Bs[lk + 2][lm] = bv.z; Bs[lk + 3][lm] = bv.w;
        __syncthreads();
#pragma unroll
        for (int kk = 0; kk < 16; kk++) {
            float4 a = *(float4*)&As[kk][ty * 4];
            float4 b = *(float4*)&Bs[kk][tx * 4];
            float aa[4] = {a.x, a.y, a.z, a.w};
            float bb[4] = {b.x, b.y, b.z, b.w};
#pragma unroll
            for (int i = 0; i < 4; i++)
#pragma unroll
                for (int j = 0; j < 4; j++) acc[i][j] += aa[i] * bb[j];
        }
    }

    const int jbase = j0 + tx * 4;
    const int s = jbase / Cq;
    const int h = (jbase % Cq) / Dq;
    const int d0 = jbase % Dq;
    float* dst = (s == 0) ? g_q : ((s == 1) ? g_k : g_v);

#pragma unroll
    for (int i = 0; i < 4; i++) {
        int t = m0 + ty * 4 + i;
        int b = t >> 11;
        int n = t & (Nq - 1);
        float4 v4 = make_float4(acc[i][0], acc[i][1], acc[i][2], acc[i][3]);
        *(float4*)&dst[(((size_t)b * Hq + h) * Nq + n) * Dq + d0] = v4;
    }
}

// ---------------------------------------------------------------------------
// Kernel 2: fused attention with tf32 tensor-core mma.
// One CTA = (b,h) x 16 query rows. 8 warps / 256 threads.
// Phase 1: S = (Q*scale) K^T via m16n8k8 tf32, Q split hi/lo (fp32-accurate Q).
// Softmax over the full 16x2048 fp32 strip in smem; normalized attn -> gmem.
// Phase 2: ctx = P V via m16n8k8 tf32, V split hi/lo.
// ---------------------------------------------------------------------------
#define SS_OFF 0
#define SS_SZ  (16 * SSTR)          // 32832
#define QH_OFF (SS_OFF + SS_SZ)     // 32832
#define QH_SZ  (16 * QSTR)          // 1040
#define QL_OFF (QH_OFF + QH_SZ)     // 33872
#define KS_OFF (QL_OFF + QH_SZ)     // 34912
#define KS_SZ  (128 * KSTR)         // 8704
#define SMEM_FLOATS (KS_OFF + KS_SZ)  // 43616 floats = 174464 B

__global__ __launch_bounds__(256) void attn_kernel(float* __restrict__ attnp)
{
    extern __shared__ float sm[];
    float* Ssm = sm + SS_OFF;
    float* Qh  = sm + QH_OFF;
    float* Ql  = sm + QL_OFF;
    float* Ks  = sm + KS_OFF;   // K chunk in phase 1, V chunk in phase 2

    const int tid  = threadIdx.x;
    const int lane = tid & 31;
    const int warp = tid >> 5;
    const int g    = lane >> 2;   // groupID  (0..7)
    const int t    = lane & 3;    // tid-in-group (0..3)

    const int bh = blockIdx.y;
    const int q0 = blockIdx.x * 16;
    const int b  = bh / Hq;
    const int h  = bh - b * Hq;

    const float* qptr = g_q + (size_t)bh * Nq * Dq;
    const float* kptr = g_k + (size_t)bh * Nq * Dq;
    const float* vptr = g_v + (size_t)bh * Nq * Dq;

    // ---- Q setup: load, scale, split into tf32 hi/lo ----
    {
        int r  = tid >> 4;
        int d4 = (tid & 15) * 4;
        float4 qv = *(const float4*)&qptr[(size_t)(q0 + r) * Dq + d4];
        float qa[4] = {qv.x * 0.125f, qv.y * 0.125f, qv.z * 0.125f, qv.w * 0.125f};
#pragma unroll
        for (int j = 0; j < 4; j++) {
            float hi = __uint_as_float(f2tf(qa[j]));
            float lo = __uint_as_float(f2tf(qa[j] - hi));
            Qh[r * QSTR + d4 + j] = hi;
            Ql[r * QSTR + d4 + j] = lo;
        }
    }
    __syncthreads();

    // ---- Preload Q A-fragments into registers (8 ksteps, hi+lo) ----
    uint32_t Ah[8][4], Al[8][4];
#pragma unroll
    for (int ks = 0; ks < 8; ks++) {
        int dd = ks * 8 + t;
        Ah[ks][0] = __float_as_uint(Qh[g * QSTR + dd]);
        Ah[ks][1] = __float_as_uint(Qh[(g + 8) * QSTR + dd]);
        Ah[ks][2] = __float_as_uint(Qh[g * QSTR + dd + 4]);
        Ah[ks][3] = __float_as_uint(Qh[(g + 8) * QSTR + dd + 4]);
        Al[ks][0] = __float_as_uint(Ql[g * QSTR + dd]);
        Al[ks][1] = __float_as_uint(Ql[(g + 8) * QSTR + dd]);
        Al[ks][2] = __float_as_uint(Ql[g * QSTR + dd + 4]);
        Al[ks][3] = __float_as_uint(Ql[(g + 8) * QSTR + dd + 4]);
    }

    // ---- Phase 1: scores ----
    for (int kt = 0; kt < Nq; kt += 128) {
        __syncthreads();
        // Load K chunk [128 keys][64 d] into Ks (stride KSTR)
#pragma unroll
        for (int i = 0; i < 8; i++) {
            int f = tid + i * 256;
            int key = f >> 4;
            int d4  = (f & 15) * 4;
            float4 kv = *(const float4*)&kptr[(size_t)(kt + key) * Dq + d4];
            *(float4*)&Ks[key * KSTR + d4] = kv;
        }
        __syncthreads();

#pragma unroll
        for (int nt = 0; nt < 2; nt++) {
            int key0 = (warp << 4) + (nt << 3);
            float acc[4] = {0.f, 0.f, 0.f, 0.f};
#pragma unroll
            for (int ks = 0; ks < 8; ks++) {
                uint32_t bb[2];
                bb[0] = f2tf(Ks[(key0 + g) * KSTR + ks * 8 + t]);
                bb[1] = f2tf(Ks[(key0 + g) * KSTR + ks * 8 + t + 4]);
                mma8(acc, Ah[ks], bb);
                mma8(acc, Al[ks], bb);
            }
            int col = kt + key0 + 2 * t;
            *(float2*)&Ssm[g * SSTR + col]       = make_float2(acc[0], acc[1]);
            *(float2*)&Ssm[(g + 8) * SSTR + col] = make_float2(acc[2], acc[3]);
        }
    }
    __syncthreads();

    // ---- Softmax over each row (16 threads per row) + write attn to gmem ----
    {
        const int r  = tid >> 4;
        const int gg = tid & 15;
        float mx = -1e30f;
#pragma unroll 4
        for (int i = 0; i < 32; i++) {
            float4 v = *(float4*)&Ssm[r * SSTR + gg * 4 + i * 64];
            mx = fmaxf(mx, fmaxf(fmaxf(v.x, v.y), fmaxf(v.z, v.w)));
        }
#pragma unroll
        for (int off = 8; off >= 1; off >>= 1)
            mx = fmaxf(mx, __shfl_xor_sync(0xffffffffu, mx, off, 16));

        float sum = 0.f;
#pragma unroll 4
        for (int i = 0; i < 32; i++) {
            int c = gg * 4 + i * 64;
            float4 v = *(float4*)&Ssm[r * SSTR + c];
            v.x = __expf(v.x - mx); v.y = __expf(v.y - mx);
            v.z = __expf(v.z - mx); v.w = __expf(v.w - mx);
            sum += v.x + v.y + v.z + v.w;
            *(float4*)&Ssm[r * SSTR + c] = v;
        }
#pragma unroll
        for (int off = 8; off >= 1; off >>= 1)
            sum += __shfl_xor_sync(0xffffffffu, sum, off, 16);
        float inv = 1.f / sum;

        float* aprow = attnp ? attnp + ((size_t)bh * Nq + (q0 + r)) * (size_t)Nq : (float*)0;
#pragma unroll 4
        for (int i = 0; i < 32; i++) {
            int c = gg * 4 + i * 64;
            float4 v = *(float4*)&Ssm[r * SSTR + c];
            v.x *= inv; v.y *= inv; v.z *= inv; v.w *= inv;
            *(float4*)&Ssm[r * SSTR + c] = v;
            if (aprow) *(float4*)&aprow[c] = v;
        }
    }
    __syncthreads();

    // ---- Phase 2: ctx = P V  (tf32 mma, V split hi/lo) ----
    // warp -> d-range (w&3)*16 (2 n-tiles of 8), kstep-half (w>>2)
    const int db = (warp & 3) * 16;
    const int kh = warp >> 2;

    float acc2[2][4];
#pragma unroll
    for (int n2 = 0; n2 < 2; n2++)
#pragma unroll
        for (int j = 0; j < 4; j++) acc2[n2][j] = 0.f;

    for (int vt = 0; vt < Nq; vt += 128) {
        __syncthreads();
#pragma unroll
        for (int i = 0; i < 8; i++) {
            int f = tid + i * 256;
            int key = f >> 4;
            int d4  = (f & 15) * 4;
            float4 vv = *(const float4*)&vptr[(size_t)(vt + key) * Dq + d4];
            *(float4*)&Ks[key * KSTR + d4] = vv;
        }
        __syncthreads();

#pragma unroll
        for (int ks = 0; ks < 8; ks++) {
            int kk = (kh * 8 + ks) * 8;     // key offset within chunk
            int col = vt + kk;
            uint32_t aa[4];
            aa[0] = f2tf(Ssm[g * SSTR + col + t]);
            aa[1] = f2tf(Ssm[(g + 8) * SSTR + col + t]);
            aa[2] = f2tf(Ssm[g * SSTR + col + t + 4]);
            aa[3] = f2tf(Ssm[(g + 8) * SSTR + col + t + 4]);
#pragma unroll
            for (int n2 = 0; n2 < 2; n2++) {
                int dd = db + n2 * 8 + g;
                float v0 = Ks[(kk + t) * KSTR + dd];
                float v1 = Ks[(kk + t + 4) * KSTR + dd];
                uint32_t bh0 = f2tf(v0);
                uint32_t bl0 = f2tf(v0 - __uint_as_float(bh0));
                uint32_t bh1 = f2tf(v1);
                uint32_t bl1 = f2tf(v1 - __uint_as_float(bh1));
                uint32_t bhv[2] = {bh0, bh1};
                uint32_t blv[2] = {bl0, bl1};
                mma8(acc2[n2], aa, bhv);
                mma8(acc2[n2], aa, blv);
            }
        }
    }

    // combine the two kstep-halves via smem partials (reuse Qh region)
    float* Pp = Qh;   // needs 16*64 = 1024 floats; QH_SZ = 1040
    __syncthreads();
    if (kh == 1) {
#pragma unroll
        for (int n2 = 0; n2 < 2; n2++) {
            int dc = db + n2 * 8 + 2 * t;
            *(float2*)&Pp[g * 64 + dc]       = make_float2(acc2[n2][0], acc2[n2][1]);
            *(float2*)&Pp[(g + 8) * 64 + dc] = make_float2(acc2[n2][2], acc2[n2][3]);
        }
    }
    __syncthreads();
    if (kh == 0) {
#pragma unroll
        for (int n2 = 0; n2 < 2; n2++) {
            int dc = db + n2 * 8 + 2 * t;
            float2 p0 = *(float2*)&Pp[g * 64 + dc];
            float2 p1 = *(float2*)&Pp[(g + 8) * 64 + dc];
            size_t tok0 = (size_t)b * Nq + (q0 + g);
            size_t tok1 = (size_t)b * Nq + (q0 + g + 8);
            *(float2*)&g_ctx[tok0 * Cq + h * Dq + dc] =
                make_float2(acc2[n2][0] + p0.x, acc2[n2][1] + p0.y);
            *(float2*)&g_ctx[tok1 * Cq + h * Dq + dc] =
                make_float2(acc2[n2][2] + p1.x, acc2[n2][3] + p1.y);
        }
    }
}

// ---------------------------------------------------------------------------
// Kernel 3: output projection (fp32 SIMT, unchanged from R1)
// ---------------------------------------------------------------------------
__global__ __launch_bounds__(256) void proj_gemm_kernel(
    const float* __restrict__ w, const float* __restrict__ bias,
    float* __restrict__ out)
{
    __shared__ float As[16][64];
    __shared__ float Bs[16][64];

    const int tid = threadIdx.x;
    const int m0 = blockIdx.y * 64;
    const int j0 = blockIdx.x * 64;
    const int lm = tid >> 2;
    const int lk = (tid & 3) * 4;
    const int ty = tid >> 4;
    const int tx = tid & 15;

    float acc[4][4];
#pragma unroll
    for (int i = 0; i < 4; i++)
#pragma unroll
        for (int j = 0; j < 4; j++) acc[i][j] = 0.f;

    for (int k0 = 0; k0 < Cq; k0 += 16) {
        float4 av = *(const float4*)&g_ctx[(size_t)(m0 + lm) * Cq + k0 + lk];
        float4 bv = *(const float4*)&w[(size_t)(j0 + lm) * Cq + k0 + lk];
        __syncthreads();
        As[lk + 0][lm] = av.x; As[lk + 1][lm] = av.y;
        As[lk + 2][lm] = av.z; As[lk + 3][lm] = av.w;
        Bs[lk + 0][lm] = bv.x; Bs[lk + 1][lm] = bv.y;
        Bs[lk + 2][lm] = bv.z; Bs[lk + 3][lm] = bv.w;
        __syncthreads();
#pragma unroll
        for (int kk = 0; kk < 16; kk++) {
            float4 a = *(float4*)&As[kk][ty * 4];
            float4 b4 = *(float4*)&Bs[kk][tx * 4];
            float aa[4] = {a.x, a.y, a.z, a.w};
            float bb[4] = {b4.x, b4.y, b4.z, b4.w};
#pragma unroll
            for (int i = 0; i < 4; i++)
#pragma unroll
                for (int j = 0; j < 4; j++) acc[i][j] += aa[i] * bb[j];
        }
    }

    float4 bv = *(const float4*)&bias[j0 + tx * 4];
#pragma unroll
    for (int i = 0; i < 4; i++) {
        float4 o = make_float4(acc[i][0] + bv.x, acc[i][1] + bv.y,
                               acc[i][2] + bv.z, acc[i][3] + bv.w);
        *(float4*)&out[(size_t)(m0 + ty * 4 + i) * Cq + j0 + tx * 4] = o;
    }
}

// ---------------------------------------------------------------------------
extern "C" void kernel_launch(void* const* d_in, const int* in_sizes, int n_in,
                              void* d_out, int out_size)
{
    const float* x      = (const float*)d_in[0];
    const float* w_qkv  = (const float*)d_in[1];
    const float* w_proj = (const float*)d_in[2];
    const float* b_proj = (const float*)d_in[3];

    const size_t out_elems  = (size_t)Mq * Cq;
    const size_t attn_elems = (size_t)BHq * Nq * (size_t)Nq;

    float* outp  = nullptr;
    float* attnp = nullptr;
    if ((size_t)out_size >= out_elems + attn_elems) {
        outp  = (float*)d_out;
        attnp = (float*)d_out + out_elems;
    } else if ((size_t)out_size == attn_elems) {
        attnp = (float*)d_out;
    } else {
        outp = (float*)d_out;
    }

    qkv_gemm_kernel<<<dim3(QKVq / 64, Mq / 64), 256>>>(x, w_qkv);

    static const int smem_bytes = SMEM_FLOATS * 4;   // 174464
    cudaFuncSetAttribute(attn_kernel, cudaFuncAttributeMaxDynamicSharedMemorySize,
                         smem_bytes);
    attn_kernel<<<dim3(Nq / 16, BHq), 256, smem_bytes>>>(attnp);

    if (outp) {
        proj_gemm_kernel<<<dim3(Cq / 64, Mq / 64), 256>>>(w_proj, b_proj, outp);
    }
}